// round 16
// baseline (speedup 1.0000x reference)
#include <cuda_runtime.h>
#include <math.h>

// ---------------------------------------------------------------------------
// Bregman divergence via 1-D tabulation with the KL x*log(x) folded into Py:
//   Py(x) = F(x) + c*x*log(max(x,1e-10))
//   Gp(x) = G(x) + c
//   div   = Py(y) - Py(y0) - (Gp(y0) + c*log(max(y0,1e-10)))*dy + 0.5*a*dy^2
// F(x) = sum_j v_j*(H_j(x)-H_j(0)),  G(x) = sum_j v_j*act_j(w_j x+b_j).
// Main path specialised for n4 = 2^19: 512 blocks x 256 threads, FOUR flat
// float4-pairs per thread (8 front-batched LDG.128, 16 independent lookups,
// 64-reg budget) -> breaks the 32-reg element serialization seen at k=2.
// Split smem tables (float2 tabY + float4 tab0), PDL overlap with node_kernel.
// ---------------------------------------------------------------------------

#define TN     512
#define NGRP   21
#define NNEUR  126
#define EPSF   1e-3f

__device__ float2 g_node[TN + 1];   // (Py, Gp) at node i

// -------- precompute: one block per node, one THREAD per neuron -------------
__global__ __launch_bounds__(128)
void node_kernel(const float* __restrict__ v,
                 const float* __restrict__ w,
                 const float* __restrict__ b,
                 const float* __restrict__ C) {
    int node = blockIdx.x;                       // 0..TN
    int j = threadIdx.x;                         // 0..127 (126 neurons)
    float x = (float)node * (1.0f / (float)TN);

    float accF = 0.0f, accG = 0.0f;
    if (j < NNEUR) {
        int g = j / NGRP;
        float wj = __ldg(w + j), bj = __ldg(b + j), vj = __ldg(v + j);
        bool  small = fabsf(wj) < 1e-12f;
        float rw = 1.0f / (small ? 1.0f : wj);
        float u  = fmaf(wj, x, bj);

        float act, hh;
        if (g == 0) {                            // act=u^3, H=u^4/(4w)
            float u2 = u * u;
            act = u2 * u;
            float b2 = bj * bj;
            hh = (u2 * u2 - b2 * b2) * (0.25f * rw);
        } else if (g == 1) {                     // act=u^2, H=u^3/(3w)
            float u2 = u * u;
            act = u2;
            hh = (u2 * u - bj * bj * bj) * (rw * (1.0f / 3.0f));
        } else if (g == 2) {                     // act=sqrt(u+), H=(2/3)u+^1.5/w
            float uc = fmaxf(u, 0.0f);
            float s  = sqrtf(uc);
            act = s;
            float bc = fmaxf(bj, 0.0f);
            hh = (2.0f / 3.0f) * rw * (uc * s - bc * sqrtf(bc));
        } else if (g == 3) {                     // act=u+^(1/3), H=0.75 u+^(4/3)/w
            float uc = fmaxf(u, 0.0f);
            float cb = cbrtf(uc);
            act = cb;
            float bc = fmaxf(bj, 0.0f);
            hh = 0.75f * rw * (uc * cb - bc * cbrtf(bc));
        } else if (g == 4) {                     // act=log(u+ + eps)
            float U  = fmaxf(u, 0.0f) + EPSF;
            float lu = logf(U);
            act = lu;
            if (u >= 0.0f && bj >= 0.0f) {
                float B = bj + EPSF;
                hh = fmaf(x, lu - 1.0f, (B * rw) * log1pf(wj * x / B));
            } else {
                float B  = fmaxf(bj, 0.0f) + EPSF;
                float lb = logf(B);
                hh = (U * (lu - 1.0f) - B * (lb - 1.0f)) * rw;
            }
        } else {                                 // act=exp(u), H=exp(u)/w
            float e = expf(u);
            act = e;
            float t = wj * x;
            float P = 1.0f + t * (0.5f + t * ((1.0f / 6.0f)
                          + t * ((1.0f / 24.0f) + t * (1.0f / 120.0f))));
            hh = expf(bj) * x * P;
        }
        accG = vj * act;
        accF = small ? accG * x : vj * hh;
    }

    #pragma unroll
    for (int s = 16; s > 0; s >>= 1) {
        accF += __shfl_xor_sync(0xFFFFFFFFu, accF, s);
        accG += __shfl_xor_sync(0xFFFFFFFFu, accG, s);
    }
    __shared__ float2 part[4];
    if ((j & 31) == 0) part[j >> 5] = make_float2(accF, accG);
    __syncthreads();
    if (j == 0) {
        float F = part[0].x + part[1].x + part[2].x + part[3].x;
        float G = part[0].y + part[1].y + part[2].y + part[3].y;
        float c = __ldg(C);
        float Py = fmaf(c * x, logf(fmaxf(x, 1e-10f)), F);
        g_node[node] = make_float2(Py, G + c);
    }
}

// ------------------------------- element math -------------------------------
__device__ __forceinline__ float bregman_elem(float y, float y0, float a, float c,
                                              const float2* __restrict__ tabY,
                                              const float4* __restrict__ tab0) {
    float ty = y * (float)TN;
    int   iy = min((int)ty, TN - 1);
    float fy = ty - (float)iy;
    float2 ey = tabY[iy];                        // (Py, dPy) packed 8B stride
    float PY = fmaf(fy, ey.y, ey.x);

    float t0 = y0 * (float)TN;
    int   i0 = min((int)t0, TN - 1);
    float f0 = t0 - (float)i0;
    float4 e0 = tab0[i0];                        // (Py, dPy, Gp, dGp)
    float P0 = fmaf(f0, e0.y, e0.x);
    float G0 = fmaf(f0, e0.w, e0.z);

    float dy = y - y0;
    float L0 = __logf(fmaxf(y0, 1e-10f));
    float slope = fmaf(c, L0, G0);               // G + c + c*log(y0s)
    float d = PY - P0;
    d = fmaf(-slope, dy, d);
    d = fmaf(0.5f * a * dy, dy, d);
    return d;
}

__device__ __forceinline__ float4 bregman_vec(float4 yv, float4 y0v, float a, float c,
                                              const float2* __restrict__ tabY,
                                              const float4* __restrict__ tab0) {
    float4 o;
    o.x = bregman_elem(yv.x, y0v.x, a, c, tabY, tab0);
    o.y = bregman_elem(yv.y, y0v.y, a, c, tabY, tab0);
    o.z = bregman_elem(yv.z, y0v.z, a, c, tabY, tab0);
    o.w = bregman_elem(yv.w, y0v.w, a, c, tabY, tab0);
    return o;
}

// ------------------ specialised main: n4 == 4 * 512 * 256 -------------------
#define SP_GRID  512
#define SP_BLK   256

__global__ __launch_bounds__(SP_BLK, 4)
void main4_kernel(const float4* __restrict__ Y, const float4* __restrict__ Y0,
                  const float* __restrict__ A, const float* __restrict__ C,
                  float4* __restrict__ OUT) {
    __shared__ float2 tabY[TN];  // (Py, dPy)         : 4 KB
    __shared__ float4 tab0[TN];  // (Py, dPy, Gp, dGp): 8 KB

    const int q = SP_GRID * SP_BLK;              // 131072
    int t = blockIdx.x * SP_BLK + threadIdx.x;

    // 8 front-batched LDG.128 issued BEFORE the PDL wait — they fly while
    // node_kernel drains.
    float4 ya  = __ldg(Y  + t);
    float4 y0a = __ldg(Y0 + t);
    float4 yb  = __ldg(Y  + t + q);
    float4 y0b = __ldg(Y0 + t + q);
    float4 yc  = __ldg(Y  + t + 2 * q);
    float4 y0c = __ldg(Y0 + t + 2 * q);
    float4 yd  = __ldg(Y  + t + 3 * q);
    float4 y0d = __ldg(Y0 + t + 3 * q);
    float a = __ldg(A);
    float c = __ldg(C);

    // Wait for node_kernel completion (+ memory flush) before reading g_node.
    cudaGridDependencySynchronize();

    #pragma unroll
    for (int k = 0; k < TN; k += SP_BLK) {
        int i = threadIdx.x + k;
        float2 n0 = g_node[i];
        float2 n1 = g_node[i + 1];
        float dP = n1.x - n0.x;
        tabY[i] = make_float2(n0.x, dP);
        tab0[i] = make_float4(n0.x, dP, n0.y, n1.y - n0.y);
    }
    __syncthreads();

    OUT[t]         = bregman_vec(ya, y0a, a, c, tabY, tab0);
    OUT[t + q]     = bregman_vec(yb, y0b, a, c, tabY, tab0);
    OUT[t + 2 * q] = bregman_vec(yc, y0c, a, c, tabY, tab0);
    OUT[t + 3 * q] = bregman_vec(yd, y0d, a, c, tabY, tab0);
}

// ------------------ generic fallback (any n4) -------------------------------
#define MAIN_GRID  740   // 148 SMs x 5 blocks: one wave
#define MAIN_BLK   256

__global__ __launch_bounds__(MAIN_BLK, 5)
void main_kernel(const float4* __restrict__ Y, const float4* __restrict__ Y0,
                 const float* __restrict__ A, const float* __restrict__ C,
                 float4* __restrict__ OUT, int n4) {
    __shared__ float2 tabY[TN];
    __shared__ float4 tab0[TN];
    for (int i = threadIdx.x; i < TN; i += MAIN_BLK) {
        float2 n0 = g_node[i];
        float2 n1 = g_node[i + 1];
        float dP = n1.x - n0.x;
        tabY[i] = make_float2(n0.x, dP);
        tab0[i] = make_float4(n0.x, dP, n0.y, n1.y - n0.y);
    }
    __syncthreads();

    float a = __ldg(A);
    float c = __ldg(C);
    const int stride = MAIN_GRID * MAIN_BLK;
    int idx = blockIdx.x * MAIN_BLK + threadIdx.x;
    if (idx >= n4) return;

    float4 ya  = __ldg(Y  + idx);
    float4 y0a = __ldg(Y0 + idx);
    int nidx = idx + stride;
    while (nidx < n4) {
        float4 yb  = __ldg(Y  + nidx);
        float4 y0b = __ldg(Y0 + nidx);
        OUT[idx] = bregman_vec(ya, y0a, a, c, tabY, tab0);
        ya = yb; y0a = y0b;
        idx = nidx;
        nidx = idx + stride;
    }
    OUT[idx] = bregman_vec(ya, y0a, a, c, tabY, tab0);
}

// scalar tail (n % 4): reads g_node directly
__global__ void tail_kernel(const float* __restrict__ Y, const float* __restrict__ Y0,
                            const float* __restrict__ A, const float* __restrict__ C,
                            float* __restrict__ OUT, int start, int n) {
    int i = start + blockIdx.x * blockDim.x + threadIdx.x;
    if (i >= n) return;
    float y = Y[i], y0 = Y0[i];
    float a = __ldg(A), c = __ldg(C);

    float ty = y * (float)TN;
    int   iy = min((int)ty, TN - 1);
    float fy = ty - (float)iy;
    float2 n0 = g_node[iy], n1 = g_node[iy + 1];
    float PY = fmaf(fy, n1.x - n0.x, n0.x);

    float t0 = y0 * (float)TN;
    int   i0 = min((int)t0, TN - 1);
    float f0 = t0 - (float)i0;
    float2 m0 = g_node[i0], m1 = g_node[i0 + 1];
    float P0 = fmaf(f0, m1.x - m0.x, m0.x);
    float G0 = fmaf(f0, m1.y - m0.y, m0.y);

    float dy = y - y0;
    float L0 = logf(fmaxf(y0, 1e-10f));
    float d = PY - P0;
    d = fmaf(-fmaf(c, L0, G0), dy, d);
    d = fmaf(0.5f * a * dy, dy, d);
    OUT[i] = d;
}

// ------------------------------- launch -------------------------------------
extern "C" void kernel_launch(void* const* d_in, const int* in_sizes, int n_in,
                              void* d_out, int out_size) {
    const float* y  = (const float*)d_in[0];
    const float* y0 = (const float*)d_in[1];
    const float* v  = (const float*)d_in[2];
    const float* w  = (const float*)d_in[3];
    const float* b  = (const float*)d_in[4];
    const float* a  = (const float*)d_in[5];
    const float* c  = (const float*)d_in[6];

    node_kernel<<<TN + 1, 128>>>(v, w, b, c);

    int n  = out_size;
    int n4 = n >> 2;
    if (n4 == 4 * SP_GRID * SP_BLK) {
        // PDL launch: main4 starts while node_kernel drains; it waits inside
        // via cudaGridDependencySynchronize() before reading g_node.
        cudaLaunchConfig_t cfg = {};
        cfg.gridDim  = dim3(SP_GRID, 1, 1);
        cfg.blockDim = dim3(SP_BLK, 1, 1);
        cfg.dynamicSmemBytes = 0;
        cfg.stream = 0;
        cudaLaunchAttribute attrs[1];
        attrs[0].id = cudaLaunchAttributeProgrammaticStreamSerialization;
        attrs[0].val.programmaticStreamSerializationAllowed = 1;
        cfg.attrs = attrs;
        cfg.numAttrs = 1;
        cudaLaunchKernelEx(&cfg, main4_kernel,
                           (const float4*)y, (const float4*)y0,
                           a, c, (float4*)d_out);
    } else if (n4 > 0) {
        main_kernel<<<MAIN_GRID, MAIN_BLK>>>((const float4*)y, (const float4*)y0,
                                             a, c, (float4*)d_out, n4);
    }
    int rem = n & 3;
    if (rem)
        tail_kernel<<<1, 32>>>(y, y0, a, c, (float*)d_out, n4 << 2, n);
}